// round 1
// baseline (speedup 1.0000x reference)
#include <cuda_runtime.h>
#include <math.h>

// Problem constants
#define Bc 32
#define Ac 5
#define Hc 64
#define Wc 64
#define HWc 4096          // H*W
#define Gc 16
#define NCLS 80
#define CHc 86            // 6 + NUM_CLASSES channels per anchor

// Accumulators: 0 = conf sq-sum (bulk + obj corrections), 1 = coord sq-sum,
//               2 = class NLL sum, 3 = theta smooth-L1 sum
__device__ float g_acc[4];

__constant__ float c_aw[5] = {1.3221f, 3.19275f, 5.05587f, 9.47112f, 11.2364f};
__constant__ float c_ah[5] = {1.73145f, 4.00944f, 8.09892f, 4.84053f, 10.0071f};
__constant__ float c_aa[5] = {0.0f, 0.3927f, 0.7854f, 1.1781f, 1.5708f};

__device__ __forceinline__ float sigf(float x) {
    return 1.0f / (1.0f + expf(-x));
}

__global__ void k_zero() {
    if (threadIdx.x < 4) g_acc[threadIdx.x] = 0.0f;
}

// Bulk conf term: sum over all (b, a, hw) of sigmoid(out[b,a,4,hw])^2.
// One block per (b,a) chunk (160 blocks), contiguous 16KB each.
__global__ __launch_bounds__(256) void k_conf(const float* __restrict__ out) {
    const float4* p = reinterpret_cast<const float4*>(
        out + (size_t)(blockIdx.x * CHc + 4) * HWc);
    float s = 0.0f;
    #pragma unroll
    for (int i = threadIdx.x; i < HWc / 4; i += 256) {
        float4 v = p[i];
        float a = sigf(v.x), b = sigf(v.y), c = sigf(v.z), d = sigf(v.w);
        s += a * a + b * b + c * c + d * d;
    }
    // warp reduce
    #pragma unroll
    for (int o = 16; o > 0; o >>= 1) s += __shfl_xor_sync(0xffffffffu, s, o);
    __shared__ float sm[8];
    int lane = threadIdx.x & 31, w = threadIdx.x >> 5;
    if (lane == 0) sm[w] = s;
    __syncthreads();
    if (w == 0) {
        s = (lane < 8) ? sm[lane] : 0.0f;
        #pragma unroll
        for (int o = 4; o > 0; o >>= 1) s += __shfl_xor_sync(0xffffffffu, s, o);
        if (lane == 0) atomicAdd(&g_acc[0], s);
    }
}

// Per-ground-truth sparse terms. One warp per gt (B*G = 512 warps).
__global__ __launch_bounds__(128) void k_gt(const float* __restrict__ out,
                                            const float* __restrict__ gtb,
                                            const int* __restrict__ gtc) {
    int warp = (blockIdx.x * blockDim.x + threadIdx.x) >> 5;
    int lane = threadIdx.x & 31;
    if (warp >= Bc * Gc) return;
    int b = warp / Gc;
    int g = warp - b * Gc;

    const float* box = gtb + (size_t)(b * Gc + g) * 5;
    float gx  = box[0] * (float)Wc;
    float gy  = box[1] * (float)Hc;
    float gw  = box[2] * (float)Wc;
    float gh  = box[3] * (float)Hc;
    float gth = box[4] * 0.39269908169872414f;  // pi/8

    // best anchor: argmax cos(0.25*(gth - aa)), strict > keeps first max (jnp.argmax)
    int best = 0;
    float iou_best = cosf(0.25f * (gth - c_aa[0]));
    #pragma unroll
    for (int a = 1; a < 5; a++) {
        float v = cosf(0.25f * (gth - c_aa[a]));
        if (v > iou_best) { iou_best = v; best = a; }
    }

    int gi = min(max((int)gx, 0), Wc - 1);
    int gj = min(max((int)gy, 0), Hc - 1);
    int cell = gj * Wc + gi;

    size_t base = (size_t)(b * Ac + best) * CHc * HWc + cell;

    // class log-softmax over channels 6..85 (stride HWc), warp-cooperative
    float x0 = out[base + (size_t)(6 + lane) * HWc];
    float x1 = out[base + (size_t)(6 + lane + 32) * HWc];
    float x2 = (lane < 16) ? out[base + (size_t)(6 + lane + 64) * HWc] : -INFINITY;
    float m = fmaxf(fmaxf(x0, x1), x2);
    #pragma unroll
    for (int o = 16; o > 0; o >>= 1) m = fmaxf(m, __shfl_xor_sync(0xffffffffu, m, o));
    float e = expf(x0 - m) + expf(x1 - m) + ((lane < 16) ? expf(x2 - m) : 0.0f);
    #pragma unroll
    for (int o = 16; o > 0; o >>= 1) e += __shfl_xor_sync(0xffffffffu, e, o);
    float lse = m + logf(e);

    if (lane == 0) {
        int cls = gtc[b * Gc + g];
        float xc = out[base + (size_t)(6 + cls) * HWc];
        float nll = lse - xc;

        // coord targets
        float tx  = gx - (float)gi;
        float ty  = gy - (float)gj;
        float tw  = logf(fmaxf(gw, 1.0f) / c_aw[best]);
        float th  = logf(fmaxf(gh, 1.0f) / c_ah[best]);
        float tth = gth - c_aa[best];

        float c0 = sigf(out[base + 0 * (size_t)HWc]);
        float c1 = sigf(out[base + 1 * (size_t)HWc]);
        float c2 = out[base + 2 * (size_t)HWc];
        float c3 = out[base + 3 * (size_t)HWc];
        float d0 = c0 - tx, d1 = c1 - ty, d2 = c2 - tw, d3 = c3 - th;
        float coord_sq = d0 * d0 + d1 * d1 + d2 * d2 + d3 * d3;

        // conf correction at obj cell: 25*(conf - iou)^2 replaces conf^2
        float cf = sigf(out[base + 4 * (size_t)HWc]);
        float dc = cf - iou_best;
        float conf_corr = 25.0f * dc * dc - cf * cf;

        // theta smooth-L1
        float t = out[base + 5 * (size_t)HWc];
        float d = fabsf(t - tth);
        float sl = (d < 1.0f) ? 0.5f * d * d : d - 0.5f;

        atomicAdd(&g_acc[0], conf_corr);
        atomicAdd(&g_acc[1], coord_sq);
        atomicAdd(&g_acc[2], nll);
        atomicAdd(&g_acc[3], sl);
    }
}

__global__ void k_finalize(float* __restrict__ o) {
    if (threadIdx.x != 0 || blockIdx.x != 0) return;
    const float n = (float)(Bc * Gc);  // 512 distinct obj positions (cells are a per-batch permutation)
    float loss_conf  = g_acc[0] / (float)((size_t)Bc * Ac * HWc);
    float loss_coord = 5.0f * g_acc[1] / (float)((size_t)Bc * Ac * 4 * HWc);
    float loss_cls   = 2.0f * g_acc[2] / n;           // CLASS_SCALE * 2
    float loss_theta = 5.0f * g_acc[3] / n;           // THETA_SCALE
    o[0] = loss_coord + loss_conf + loss_cls + loss_theta;
    o[1] = loss_coord;
    o[2] = loss_conf;
    o[3] = loss_cls;
    o[4] = loss_theta;
}

extern "C" void kernel_launch(void* const* d_in, const int* in_sizes, int n_in,
                              void* d_out, int out_size) {
    const float* out  = (const float*)d_in[0];
    const float* gtb  = (const float*)d_in[1];
    const int*   gtc  = (const int*)d_in[2];
    float* o = (float*)d_out;

    k_zero<<<1, 32>>>();
    k_conf<<<Bc * Ac, 256>>>(out);
    k_gt<<<(Bc * Gc * 32 + 127) / 128, 128>>>(out, gtb, gtc);
    k_finalize<<<1, 32>>>(o);
}

// round 2
// speedup vs baseline: 1.0022x; 1.0022x over previous
#include <cuda_runtime.h>
#include <math.h>

#define Bc 32
#define Ac 5
#define Hc 64
#define Wc 64
#define HWc 4096
#define Gc 16
#define NCLS 80
#define CHc 86
#define NBLK (Bc * Ac)   // 160

// Per-block partials: [block][0]=conf sq-sum, [1]=coord, [2]=cls nll, [3]=theta
__device__ float g_part[NBLK][4];
__device__ unsigned int g_cnt;   // zero at load; last block resets to 0 each call

__constant__ float c_aw[5] = {1.3221f, 3.19275f, 5.05587f, 9.47112f, 11.2364f};
__constant__ float c_ah[5] = {1.73145f, 4.00944f, 8.09892f, 4.84053f, 10.0071f};
__constant__ float c_aa[5] = {0.0f, 0.3927f, 0.7854f, 1.1781f, 1.5708f};

__device__ __forceinline__ float sigf(float x) {
    return 1.0f / (1.0f + __expf(-x));
}

__global__ __launch_bounds__(256) void k_fused(const float* __restrict__ out,
                                               const float* __restrict__ gtb,
                                               const int* __restrict__ gtc,
                                               float* __restrict__ o) {
    __shared__ float s_acc[4];
    __shared__ int s_last;
    const int tid  = threadIdx.x;
    const int lane = tid & 31;
    const int wid  = tid >> 5;
    const int bid  = blockIdx.x;

    if (tid < 4) s_acc[tid] = 0.0f;
    __syncthreads();

    // ---- bulk conf term: sigmoid(out[b,a,4,:])^2 over this block's chunk ----
    {
        const float4* p = reinterpret_cast<const float4*>(
            out + (size_t)(bid * CHc + 4) * HWc);
        float s = 0.0f;
        #pragma unroll
        for (int i = tid; i < HWc / 4; i += 256) {
            float4 v = p[i];
            float a = sigf(v.x), b = sigf(v.y), c = sigf(v.z), d = sigf(v.w);
            s += a * a + b * b + c * c + d * d;
        }
        #pragma unroll
        for (int off = 16; off > 0; off >>= 1)
            s += __shfl_xor_sync(0xffffffffu, s, off);
        if (lane == 0) atomicAdd(&s_acc[0], s);
    }

    // ---- per-gt sparse terms: global warps 0..511 handle one gt each ----
    const int gwarp = bid * 8 + wid;
    if (gwarp < Bc * Gc) {
        const int b = gwarp / Gc;
        const int g = gwarp - b * Gc;

        const float* box = gtb + (size_t)(b * Gc + g) * 5;
        float gx  = box[0] * (float)Wc;
        float gy  = box[1] * (float)Hc;
        float gw  = box[2] * (float)Wc;
        float gh  = box[3] * (float)Hc;
        float gth = box[4] * 0.39269908169872414f;  // pi/8

        int best = 0;
        float iou_best = cosf(0.25f * (gth - c_aa[0]));
        #pragma unroll
        for (int a = 1; a < 5; a++) {
            float v = cosf(0.25f * (gth - c_aa[a]));
            if (v > iou_best) { iou_best = v; best = a; }
        }

        int gi = min(max((int)gx, 0), Wc - 1);
        int gj = min(max((int)gy, 0), Hc - 1);
        int cell = gj * Wc + gi;
        size_t base = (size_t)(b * Ac + best) * CHc * HWc + cell;

        // warp-cooperative log-softmax over 80 class channels (stride HWc)
        float x0 = out[base + (size_t)(6 + lane) * HWc];
        float x1 = out[base + (size_t)(6 + lane + 32) * HWc];
        float x2 = (lane < 16) ? out[base + (size_t)(6 + lane + 64) * HWc] : -INFINITY;
        float m = fmaxf(fmaxf(x0, x1), x2);
        #pragma unroll
        for (int off = 16; off > 0; off >>= 1)
            m = fmaxf(m, __shfl_xor_sync(0xffffffffu, m, off));
        float e = __expf(x0 - m) + __expf(x1 - m) + ((lane < 16) ? __expf(x2 - m) : 0.0f);
        #pragma unroll
        for (int off = 16; off > 0; off >>= 1)
            e += __shfl_xor_sync(0xffffffffu, e, off);
        float lse = m + __logf(e);

        if (lane == 0) {
            int cls = gtc[b * Gc + g];
            float xc = out[base + (size_t)(6 + cls) * HWc];
            float nll = lse - xc;

            float tx  = gx - (float)gi;
            float ty  = gy - (float)gj;
            float tw  = __logf(fmaxf(gw, 1.0f) / c_aw[best]);
            float th  = __logf(fmaxf(gh, 1.0f) / c_ah[best]);
            float tth = gth - c_aa[best];

            float c0 = sigf(out[base + 0 * (size_t)HWc]);
            float c1 = sigf(out[base + 1 * (size_t)HWc]);
            float c2 = out[base + 2 * (size_t)HWc];
            float c3 = out[base + 3 * (size_t)HWc];
            float d0 = c0 - tx, d1 = c1 - ty, d2 = c2 - tw, d3 = c3 - th;
            float coord_sq = d0 * d0 + d1 * d1 + d2 * d2 + d3 * d3;

            float cf = sigf(out[base + 4 * (size_t)HWc]);
            float dc = cf - iou_best;
            float conf_corr = 25.0f * dc * dc - cf * cf;

            float t = out[base + 5 * (size_t)HWc];
            float d = fabsf(t - tth);
            float sl = (d < 1.0f) ? 0.5f * d * d : d - 0.5f;

            atomicAdd(&s_acc[0], conf_corr);
            atomicAdd(&s_acc[1], coord_sq);
            atomicAdd(&s_acc[2], nll);
            atomicAdd(&s_acc[3], sl);
        }
    }

    __syncthreads();
    if (tid < 4) g_part[bid][tid] = s_acc[tid];
    __threadfence();
    __syncthreads();
    if (tid == 0) {
        unsigned int t = atomicAdd(&g_cnt, 1u);
        s_last = (t == (unsigned int)(NBLK - 1)) ? 1 : 0;
    }
    __syncthreads();
    if (!s_last) return;

    // ---- last block: reduce 160x4 partials, finalize, reset counter ----
    __threadfence();
    float a0 = 0.0f, a1 = 0.0f, a2 = 0.0f, a3 = 0.0f;
    if (tid < NBLK) {
        a0 = g_part[tid][0];
        a1 = g_part[tid][1];
        a2 = g_part[tid][2];
        a3 = g_part[tid][3];
    }
    #pragma unroll
    for (int off = 16; off > 0; off >>= 1) {
        a0 += __shfl_xor_sync(0xffffffffu, a0, off);
        a1 += __shfl_xor_sync(0xffffffffu, a1, off);
        a2 += __shfl_xor_sync(0xffffffffu, a2, off);
        a3 += __shfl_xor_sync(0xffffffffu, a3, off);
    }
    __shared__ float s_red[8][4];
    if (lane == 0) {
        s_red[wid][0] = a0; s_red[wid][1] = a1;
        s_red[wid][2] = a2; s_red[wid][3] = a3;
    }
    __syncthreads();
    if (tid == 0) {
        float t0 = 0.0f, t1 = 0.0f, t2 = 0.0f, t3 = 0.0f;
        #pragma unroll
        for (int w = 0; w < 8; w++) {
            t0 += s_red[w][0]; t1 += s_red[w][1];
            t2 += s_red[w][2]; t3 += s_red[w][3];
        }
        const float n = (float)(Bc * Gc);  // 512 distinct obj cells (per-batch permutation)
        float loss_conf  = t0 / (float)((size_t)Bc * Ac * HWc);
        float loss_coord = 5.0f * t1 / (float)((size_t)Bc * Ac * 4 * HWc);
        float loss_cls   = 2.0f * t2 / n;
        float loss_theta = 5.0f * t3 / n;
        o[0] = loss_coord + loss_conf + loss_cls + loss_theta;
        o[1] = loss_coord;
        o[2] = loss_conf;
        o[3] = loss_cls;
        o[4] = loss_theta;
        g_cnt = 0;  // reset for next graph replay
    }
}

extern "C" void kernel_launch(void* const* d_in, const int* in_sizes, int n_in,
                              void* d_out, int out_size) {
    const float* out = (const float*)d_in[0];
    const float* gtb = (const float*)d_in[1];
    const int*   gtc = (const int*)d_in[2];
    float* o = (float*)d_out;
    k_fused<<<NBLK, 256>>>(out, gtb, gtc, o);
}

// round 3
// speedup vs baseline: 1.3851x; 1.3821x over previous
#include <cuda_runtime.h>
#include <math.h>

#define Bc 32
#define Ac 5
#define Hc 64
#define Wc 64
#define HWc 4096
#define Gc 16
#define NCLS 80
#define CHc 86
#define SPLIT 4
#define NBLK (Bc * Ac * SPLIT)   // 640 blocks, 256 threads, 1 float4/thread

// Per-block partials: x=conf sq-sum, y=coord, z=cls nll, w=theta
__device__ float4 g_part[NBLK];
__device__ unsigned int g_cnt;   // zero at load; last block resets each call

__constant__ float c_aw[5] = {1.3221f, 3.19275f, 5.05587f, 9.47112f, 11.2364f};
__constant__ float c_ah[5] = {1.73145f, 4.00944f, 8.09892f, 4.84053f, 10.0071f};
__constant__ float c_aa[5] = {0.0f, 0.3927f, 0.7854f, 1.1781f, 1.5708f};

__device__ __forceinline__ float sigf(float x) {
    return __fdividef(1.0f, 1.0f + __expf(-x));
}

__global__ __launch_bounds__(256) void k_fused(const float* __restrict__ out,
                                               const float* __restrict__ gtb,
                                               const int* __restrict__ gtc,
                                               float* __restrict__ o) {
    __shared__ float s_acc[4];
    __shared__ int s_last;
    const int tid  = threadIdx.x;
    const int lane = tid & 31;
    const int wid  = tid >> 5;
    const int bid  = blockIdx.x;

    if (tid < 4) s_acc[tid] = 0.0f;

    // ---- bulk conf term: this block covers 1024 floats of one (b,a) conf plane ----
    const int chunk = bid >> 2;          // which (b,a)
    const int part  = bid & 3;           // quarter of the 4096-float plane
    const float4* p = reinterpret_cast<const float4*>(
        out + (size_t)(chunk * CHc + 4) * HWc + part * (HWc / 4));
    float4 v = p[tid];                   // one independent load, issued immediately

    // ---- per-gt sparse terms: global warps in blocks 0..63 (512 warps total) ----
    const bool has_gt = (bid < 64);
    float nll = 0.0f, coord_sq = 0.0f, conf_corr = 0.0f, sl = 0.0f;
    if (has_gt) {
        const int gwarp = bid * 8 + wid;     // 0..511
        const int b = gwarp / Gc;
        const int g = gwarp - b * Gc;

        const float* box = gtb + (size_t)(b * Gc + g) * 5;
        float gx  = box[0] * (float)Wc;
        float gy  = box[1] * (float)Hc;
        float gw  = box[2] * (float)Wc;
        float gh  = box[3] * (float)Hc;
        float gth = box[4] * 0.39269908169872414f;  // pi/8

        int best = 0;
        float iou_best = cosf(0.25f * (gth - c_aa[0]));
        #pragma unroll
        for (int a = 1; a < 5; a++) {
            float t = cosf(0.25f * (gth - c_aa[a]));
            if (t > iou_best) { iou_best = t; best = a; }
        }

        int gi = min(max((int)gx, 0), Wc - 1);
        int gj = min(max((int)gy, 0), Hc - 1);
        int cell = gj * Wc + gi;
        size_t base = (size_t)(b * Ac + best) * CHc * HWc + cell;

        // warp-cooperative log-softmax over 80 class channels (stride HWc)
        float x0 = out[base + (size_t)(6 + lane) * HWc];
        float x1 = out[base + (size_t)(6 + lane + 32) * HWc];
        float x2 = (lane < 16) ? out[base + (size_t)(6 + lane + 64) * HWc] : -INFINITY;
        float m = fmaxf(fmaxf(x0, x1), x2);
        #pragma unroll
        for (int off = 16; off > 0; off >>= 1)
            m = fmaxf(m, __shfl_xor_sync(0xffffffffu, m, off));
        float e = __expf(x0 - m) + __expf(x1 - m) + ((lane < 16) ? __expf(x2 - m) : 0.0f);
        #pragma unroll
        for (int off = 16; off > 0; off >>= 1)
            e += __shfl_xor_sync(0xffffffffu, e, off);
        float lse = m + __logf(e);

        if (lane == 0) {
            int cls = gtc[b * Gc + g];
            float xc = out[base + (size_t)(6 + cls) * HWc];
            nll = lse - xc;

            float tx  = gx - (float)gi;
            float ty  = gy - (float)gj;
            float tw  = __logf(fmaxf(gw, 1.0f) / c_aw[best]);
            float th  = __logf(fmaxf(gh, 1.0f) / c_ah[best]);
            float tth = gth - c_aa[best];

            float c0 = sigf(out[base + 0 * (size_t)HWc]);
            float c1 = sigf(out[base + 1 * (size_t)HWc]);
            float c2 = out[base + 2 * (size_t)HWc];
            float c3 = out[base + 3 * (size_t)HWc];
            float d0 = c0 - tx, d1 = c1 - ty, d2 = c2 - tw, d3 = c3 - th;
            coord_sq = d0 * d0 + d1 * d1 + d2 * d2 + d3 * d3;

            float cf = sigf(out[base + 4 * (size_t)HWc]);
            float dc = cf - iou_best;
            conf_corr = 25.0f * dc * dc - cf * cf;

            float t = out[base + 5 * (size_t)HWc];
            float d = fabsf(t - tth);
            sl = (d < 1.0f) ? 0.5f * d * d : d - 0.5f;
        }
    }

    // ---- reduce bulk sigmoid^2 ----
    float a0 = sigf(v.x), b0 = sigf(v.y), c0 = sigf(v.z), d0 = sigf(v.w);
    float s = a0 * a0 + b0 * b0 + c0 * c0 + d0 * d0 + conf_corr;
    #pragma unroll
    for (int off = 16; off > 0; off >>= 1)
        s += __shfl_xor_sync(0xffffffffu, s, off);
    __syncthreads();   // s_acc init visible
    if (lane == 0) {
        atomicAdd(&s_acc[0], s);
        if (has_gt) {
            atomicAdd(&s_acc[1], coord_sq);
            atomicAdd(&s_acc[2], nll);
            atomicAdd(&s_acc[3], sl);
        }
    }
    __syncthreads();

    if (tid == 0) {
        float4 w = make_float4(s_acc[0], s_acc[1], s_acc[2], s_acc[3]);
        g_part[bid] = w;
        __threadfence();
        unsigned int t = atomicAdd(&g_cnt, 1u);
        s_last = (t == (unsigned int)(NBLK - 1)) ? 1 : 0;
    }
    __syncthreads();
    if (!s_last) return;

    // ---- last block: reduce 640 float4 partials ----
    __threadfence();
    float4 acc = make_float4(0.f, 0.f, 0.f, 0.f);
    for (int i = tid; i < NBLK; i += 256) {
        float4 w = g_part[i];
        acc.x += w.x; acc.y += w.y; acc.z += w.z; acc.w += w.w;
    }
    #pragma unroll
    for (int off = 16; off > 0; off >>= 1) {
        acc.x += __shfl_xor_sync(0xffffffffu, acc.x, off);
        acc.y += __shfl_xor_sync(0xffffffffu, acc.y, off);
        acc.z += __shfl_xor_sync(0xffffffffu, acc.z, off);
        acc.w += __shfl_xor_sync(0xffffffffu, acc.w, off);
    }
    __shared__ float4 s_red[8];
    if (lane == 0) s_red[wid] = acc;
    __syncthreads();
    if (tid == 0) {
        float t0 = 0.f, t1 = 0.f, t2 = 0.f, t3 = 0.f;
        #pragma unroll
        for (int w = 0; w < 8; w++) {
            t0 += s_red[w].x; t1 += s_red[w].y;
            t2 += s_red[w].z; t3 += s_red[w].w;
        }
        const float n = (float)(Bc * Gc);  // 512 distinct obj cells (per-batch permutation)
        float loss_conf  = t0 / (float)((size_t)Bc * Ac * HWc);
        float loss_coord = 5.0f * t1 / (float)((size_t)Bc * Ac * 4 * HWc);
        float loss_cls   = 2.0f * t2 / n;
        float loss_theta = 5.0f * t3 / n;
        o[0] = loss_coord + loss_conf + loss_cls + loss_theta;
        o[1] = loss_coord;
        o[2] = loss_conf;
        o[3] = loss_cls;
        o[4] = loss_theta;
        g_cnt = 0;  // reset for next graph replay
    }
}

extern "C" void kernel_launch(void* const* d_in, const int* in_sizes, int n_in,
                              void* d_out, int out_size) {
    const float* out = (const float*)d_in[0];
    const float* gtb = (const float*)d_in[1];
    const int*   gtc = (const int*)d_in[2];
    float* o = (float*)d_out;
    k_fused<<<NBLK, 256>>>(out, gtb, gtc, o);
}

// round 5
// speedup vs baseline: 1.4146x; 1.0213x over previous
#include <cuda_runtime.h>
#include <math.h>

#define Bc 32
#define Ac 5
#define Hc 64
#define Wc 64
#define HWc 4096
#define Gc 16
#define NCLS 80
#define CHc 86
#define SPLIT 8
#define NBLK (Bc * Ac * SPLIT)   // 1280 blocks x 128 threads, 1 float4/thread

// Per-block partials: x=conf sq-sum, y=coord, z=cls nll, w=theta
__device__ float4 g_part[NBLK];
__device__ unsigned int g_cnt;   // zero at load; last block resets each call

__constant__ float c_aw[5] = {1.3221f, 3.19275f, 5.05587f, 9.47112f, 11.2364f};
__constant__ float c_ah[5] = {1.73145f, 4.00944f, 8.09892f, 4.84053f, 10.0071f};
__constant__ float c_aa[5] = {0.0f, 0.3927f, 0.7854f, 1.1781f, 1.5708f};

__device__ __forceinline__ float sigf(float x) {
    return __fdividef(1.0f, 1.0f + __expf(-x));
}

__global__ __launch_bounds__(128) void k_fused(const float* __restrict__ out,
                                               const float* __restrict__ gtb,
                                               const int* __restrict__ gtc,
                                               float* __restrict__ o) {
    __shared__ float s_acc[4];
    __shared__ int s_last;
    const int tid  = threadIdx.x;
    const int lane = tid & 31;
    const int wid  = tid >> 5;
    const int bid  = blockIdx.x;

    if (tid < 4) s_acc[tid] = 0.0f;

    // ---- per-gt inputs: start the dependent chain FIRST (blocks 0..511, warp 0) ----
    const bool has_gt = (bid < Bc * Gc) && (wid == 0);
    float bx0 = 0.f, bx1 = 0.f, bx2 = 0.f, bx3 = 0.f, bx4 = 0.f;
    int cls = 0;
    if (has_gt) {
        const float* box = gtb + (size_t)bid * 5;
        bx0 = box[0]; bx1 = box[1]; bx2 = box[2]; bx3 = box[3]; bx4 = box[4];
        cls = gtc[bid];
    }

    // ---- bulk conf term: 1 float4 per thread of one (b,a) conf plane ----
    const int chunk = bid >> 3;          // which (b,a)
    const int part  = bid & 7;           // eighth of the 4096-float plane
    const float4* p = reinterpret_cast<const float4*>(
        out + (size_t)(chunk * CHc + 4) * HWc + part * (HWc / 8));
    float4 v = p[tid];

    // ---- per-gt sparse terms ----
    float nll = 0.0f, coord_sq = 0.0f, conf_corr = 0.0f, sl = 0.0f;
    if (has_gt) {
        float gx  = bx0 * (float)Wc;
        float gy  = bx1 * (float)Hc;
        float gw  = bx2 * (float)Wc;
        float gh  = bx3 * (float)Hc;
        float gth = bx4 * 0.39269908169872414f;  // pi/8

        int best = 0;
        float iou_best = cosf(0.25f * (gth - c_aa[0]));
        #pragma unroll
        for (int a = 1; a < 5; a++) {
            float t = cosf(0.25f * (gth - c_aa[a]));
            if (t > iou_best) { iou_best = t; best = a; }
        }

        int gi = min(max((int)gx, 0), Wc - 1);
        int gj = min(max((int)gy, 0), Hc - 1);
        int cell = gj * Wc + gi;
        size_t base = (size_t)((bid / Gc) * Ac + best) * CHc * HWc + cell;

        // warp-cooperative log-softmax over 80 class channels (stride HWc)
        float x0 = out[base + (size_t)(6 + lane) * HWc];
        float x1 = out[base + (size_t)(6 + lane + 32) * HWc];
        float x2 = (lane < 16) ? out[base + (size_t)(6 + lane + 64) * HWc] : -INFINITY;
        // lane0's extra loads issued in parallel with the reduce chain
        float e0 = 0.f, e1 = 0.f, e2 = 0.f, e3 = 0.f, e4 = 0.f, e5 = 0.f, exc = 0.f;
        if (lane == 0) {
            e0 = out[base + 0 * (size_t)HWc];
            e1 = out[base + 1 * (size_t)HWc];
            e2 = out[base + 2 * (size_t)HWc];
            e3 = out[base + 3 * (size_t)HWc];
            e4 = out[base + 4 * (size_t)HWc];
            e5 = out[base + 5 * (size_t)HWc];
            exc = out[base + (size_t)(6 + cls) * HWc];
        }
        float m = fmaxf(fmaxf(x0, x1), x2);
        #pragma unroll
        for (int off = 16; off > 0; off >>= 1)
            m = fmaxf(m, __shfl_xor_sync(0xffffffffu, m, off));
        float e = __expf(x0 - m) + __expf(x1 - m) + ((lane < 16) ? __expf(x2 - m) : 0.0f);
        #pragma unroll
        for (int off = 16; off > 0; off >>= 1)
            e += __shfl_xor_sync(0xffffffffu, e, off);
        float lse = m + __logf(e);

        if (lane == 0) {
            nll = lse - exc;

            float tx  = gx - (float)gi;
            float ty  = gy - (float)gj;
            float tw  = __logf(fmaxf(gw, 1.0f) / c_aw[best]);
            float th  = __logf(fmaxf(gh, 1.0f) / c_ah[best]);
            float tth = gth - c_aa[best];

            float c0 = sigf(e0), c1 = sigf(e1);
            float d0 = c0 - tx, d1 = c1 - ty, d2 = e2 - tw, d3 = e3 - th;
            coord_sq = d0 * d0 + d1 * d1 + d2 * d2 + d3 * d3;

            float cf = sigf(e4);
            float dc = cf - iou_best;
            conf_corr = 25.0f * dc * dc - cf * cf;

            float d = fabsf(e5 - tth);
            sl = (d < 1.0f) ? 0.5f * d * d : d - 0.5f;
        }
    }

    // ---- reduce bulk sigmoid^2 (+ gt corrections folded into lane0 terms) ----
    float a0 = sigf(v.x), b0 = sigf(v.y), c0 = sigf(v.z), d0 = sigf(v.w);
    float s = a0 * a0 + b0 * b0 + c0 * c0 + d0 * d0 + conf_corr;
    #pragma unroll
    for (int off = 16; off > 0; off >>= 1)
        s += __shfl_xor_sync(0xffffffffu, s, off);
    __syncthreads();   // s_acc init visible
    if (lane == 0) {
        atomicAdd(&s_acc[0], s);
        if (has_gt) {
            atomicAdd(&s_acc[1], coord_sq);
            atomicAdd(&s_acc[2], nll);
            atomicAdd(&s_acc[3], sl);
        }
    }
    __syncthreads();

    if (tid == 0) {
        g_part[bid] = make_float4(s_acc[0], s_acc[1], s_acc[2], s_acc[3]);
        __threadfence();
        unsigned int t = atomicAdd(&g_cnt, 1u);
        s_last = (t == (unsigned int)(NBLK - 1)) ? 1 : 0;
    }
    __syncthreads();
    if (!s_last) return;

    // ---- last block: reduce 1280 float4 partials ----
    __threadfence();
    float4 acc = make_float4(0.f, 0.f, 0.f, 0.f);
    #pragma unroll
    for (int i = tid; i < NBLK; i += 128) {
        float4 w = g_part[i];
        acc.x += w.x; acc.y += w.y; acc.z += w.z; acc.w += w.w;
    }
    #pragma unroll
    for (int off = 16; off > 0; off >>= 1) {
        acc.x += __shfl_xor_sync(0xffffffffu, acc.x, off);
        acc.y += __shfl_xor_sync(0xffffffffu, acc.y, off);
        acc.z += __shfl_xor_sync(0xffffffffu, acc.z, off);
        acc.w += __shfl_xor_sync(0xffffffffu, acc.w, off);
    }
    __shared__ float4 s_red[4];
    if (lane == 0) s_red[wid] = acc;
    __syncthreads();
    if (tid == 0) {
        float t0 = 0.f, t1 = 0.f, t2 = 0.f, t3 = 0.f;
        #pragma unroll
        for (int w = 0; w < 4; w++) {
            t0 += s_red[w].x; t1 += s_red[w].y;
            t2 += s_red[w].z; t3 += s_red[w].w;
        }
        const float n = (float)(Bc * Gc);  // 512 distinct obj cells (per-batch permutation)
        float loss_conf  = t0 / (float)((size_t)Bc * Ac * HWc);
        float loss_coord = 5.0f * t1 / (float)((size_t)Bc * Ac * 4 * HWc);
        float loss_cls   = 2.0f * t2 / n;
        float loss_theta = 5.0f * t3 / n;
        o[0] = loss_coord + loss_conf + loss_cls + loss_theta;
        o[1] = loss_coord;
        o[2] = loss_conf;
        o[3] = loss_cls;
        o[4] = loss_theta;
        g_cnt = 0;  // reset for next graph replay
    }
}

extern "C" void kernel_launch(void* const* d_in, const int* in_sizes, int n_in,
                              void* d_out, int out_size) {
    const float* out = (const float*)d_in[0];
    const float* gtb = (const float*)d_in[1];
    const int*   gtc = (const int*)d_in[2];
    float* o = (float*)d_out;
    k_fused<<<NBLK, 128>>>(out, gtb, gtc, o);
}

// round 6
// speedup vs baseline: 1.5945x; 1.1271x over previous
#include <cuda_runtime.h>
#include <math.h>

#define Bc 32
#define Ac 5
#define Hc 64
#define Wc 64
#define HWc 4096
#define Gc 16
#define NCLS 80
#define CHc 86
#define SPLIT 8
#define NBLK (Bc * Ac * SPLIT)   // 1280 blocks x 128 threads, 1 float4/thread

// 32 spread accumulator slots: x=conf sq-sum, y=coord, z=cls nll, w=theta.
// Zero at module load; finalize kernel re-zeroes after reading (graph-replay safe).
__device__ float4 g_slot[32];

__constant__ float c_aw[5] = {1.3221f, 3.19275f, 5.05587f, 9.47112f, 11.2364f};
__constant__ float c_ah[5] = {1.73145f, 4.00944f, 8.09892f, 4.84053f, 10.0071f};
__constant__ float c_aa[5] = {0.0f, 0.3927f, 0.7854f, 1.1781f, 1.5708f};

__device__ __forceinline__ float sigf(float x) {
    return __fdividef(1.0f, 1.0f + __expf(-x));
}

__global__ __launch_bounds__(128) void k_main(const float* __restrict__ out,
                                              const float* __restrict__ gtb,
                                              const int* __restrict__ gtc) {
    const int tid  = threadIdx.x;
    const int lane = tid & 31;
    const int wid  = tid >> 5;
    const int bid  = blockIdx.x;

    // ---- per-gt inputs first: start the dependent chain early (blocks 0..511, warp 0) ----
    const bool has_gt = (bid < Bc * Gc) && (wid == 0);
    float bx0 = 0.f, bx1 = 0.f, bx2 = 0.f, bx3 = 0.f, bx4 = 0.f;
    int cls = 0;
    if (has_gt) {
        const float* box = gtb + (size_t)bid * 5;
        bx0 = box[0]; bx1 = box[1]; bx2 = box[2]; bx3 = box[3]; bx4 = box[4];
        cls = gtc[bid];
    }

    // ---- bulk conf term: 1 float4 per thread of one (b,a) conf plane ----
    const int chunk = bid >> 3;
    const int part  = bid & 7;
    const float4* p = reinterpret_cast<const float4*>(
        out + (size_t)(chunk * CHc + 4) * HWc + part * (HWc / 8));
    float4 v = p[tid];

    // ---- per-gt sparse terms ----
    float nll = 0.0f, coord_sq = 0.0f, conf_corr = 0.0f, sl = 0.0f;
    if (has_gt) {
        float gx  = bx0 * (float)Wc;
        float gy  = bx1 * (float)Hc;
        float gw  = bx2 * (float)Wc;
        float gh  = bx3 * (float)Hc;
        float gth = bx4 * 0.39269908169872414f;  // pi/8

        int best = 0;
        float iou_best = __cosf(0.25f * (gth - c_aa[0]));
        #pragma unroll
        for (int a = 1; a < 5; a++) {
            float t = __cosf(0.25f * (gth - c_aa[a]));
            if (t > iou_best) { iou_best = t; best = a; }
        }

        int gi = min(max((int)gx, 0), Wc - 1);
        int gj = min(max((int)gy, 0), Hc - 1);
        int cell = gj * Wc + gi;
        size_t base = (size_t)((bid / Gc) * Ac + best) * CHc * HWc + cell;

        // warp-cooperative log-softmax over 80 class channels (stride HWc)
        float x0 = out[base + (size_t)(6 + lane) * HWc];
        float x1 = out[base + (size_t)(6 + lane + 32) * HWc];
        float x2 = (lane < 16) ? out[base + (size_t)(6 + lane + 64) * HWc] : -INFINITY;
        float e0 = 0.f, e1 = 0.f, e2 = 0.f, e3 = 0.f, e4 = 0.f, e5 = 0.f, exc = 0.f;
        if (lane == 0) {   // issued in parallel with the shuffle chains
            e0 = out[base + 0 * (size_t)HWc];
            e1 = out[base + 1 * (size_t)HWc];
            e2 = out[base + 2 * (size_t)HWc];
            e3 = out[base + 3 * (size_t)HWc];
            e4 = out[base + 4 * (size_t)HWc];
            e5 = out[base + 5 * (size_t)HWc];
            exc = out[base + (size_t)(6 + cls) * HWc];
        }
        float m = fmaxf(fmaxf(x0, x1), x2);
        #pragma unroll
        for (int off = 16; off > 0; off >>= 1)
            m = fmaxf(m, __shfl_xor_sync(0xffffffffu, m, off));
        float e = __expf(x0 - m) + __expf(x1 - m) + ((lane < 16) ? __expf(x2 - m) : 0.0f);
        #pragma unroll
        for (int off = 16; off > 0; off >>= 1)
            e += __shfl_xor_sync(0xffffffffu, e, off);
        float lse = m + __logf(e);

        if (lane == 0) {
            nll = lse - exc;

            float tx  = gx - (float)gi;
            float ty  = gy - (float)gj;
            float tw  = __logf(fmaxf(gw, 1.0f) / c_aw[best]);
            float th  = __logf(fmaxf(gh, 1.0f) / c_ah[best]);
            float tth = gth - c_aa[best];

            float c0 = sigf(e0), c1 = sigf(e1);
            float d0 = c0 - tx, d1 = c1 - ty, d2 = e2 - tw, d3 = e3 - th;
            coord_sq = d0 * d0 + d1 * d1 + d2 * d2 + d3 * d3;

            float cf = sigf(e4);
            float dc = cf - iou_best;
            conf_corr = 25.0f * dc * dc - cf * cf;

            float d = fabsf(e5 - tth);
            sl = (d < 1.0f) ? 0.5f * d * d : d - 0.5f;
        }
    }

    // ---- per-warp reduce of bulk sigmoid^2 (+ conf correction on gt lane0) ----
    float a0 = sigf(v.x), b0 = sigf(v.y), c0 = sigf(v.z), d0 = sigf(v.w);
    float s = a0 * a0 + b0 * b0 + c0 * c0 + d0 * d0 + conf_corr;
    #pragma unroll
    for (int off = 16; off > 0; off >>= 1)
        s += __shfl_xor_sync(0xffffffffu, s, off);

    // ---- straight to global: return-less atomics (RED), 32-way address spread ----
    float* slot = reinterpret_cast<float*>(&g_slot[(bid * 4 + wid) & 31]);
    if (lane == 0) {
        atomicAdd(slot + 0, s);
        if (has_gt) {
            atomicAdd(slot + 1, coord_sq);
            atomicAdd(slot + 2, nll);
            atomicAdd(slot + 3, sl);
        }
    }
}

__global__ void k_finalize(float* __restrict__ o) {
    const int lane = threadIdx.x;
    float4 v = g_slot[lane];
    float t0 = v.x, t1 = v.y, t2 = v.z, t3 = v.w;
    #pragma unroll
    for (int off = 16; off > 0; off >>= 1) {
        t0 += __shfl_xor_sync(0xffffffffu, t0, off);
        t1 += __shfl_xor_sync(0xffffffffu, t1, off);
        t2 += __shfl_xor_sync(0xffffffffu, t2, off);
        t3 += __shfl_xor_sync(0xffffffffu, t3, off);
    }
    if (lane == 0) {
        const float n = (float)(Bc * Gc);  // 512 distinct obj cells (per-batch permutation)
        float loss_conf  = t0 / (float)((size_t)Bc * Ac * HWc);
        float loss_coord = 5.0f * t1 / (float)((size_t)Bc * Ac * 4 * HWc);
        float loss_cls   = 2.0f * t2 / n;
        float loss_theta = 5.0f * t3 / n;
        o[0] = loss_coord + loss_conf + loss_cls + loss_theta;
        o[1] = loss_coord;
        o[2] = loss_conf;
        o[3] = loss_cls;
        o[4] = loss_theta;
    }
    g_slot[lane] = make_float4(0.f, 0.f, 0.f, 0.f);  // reset for next replay
}

extern "C" void kernel_launch(void* const* d_in, const int* in_sizes, int n_in,
                              void* d_out, int out_size) {
    const float* out = (const float*)d_in[0];
    const float* gtb = (const float*)d_in[1];
    const int*   gtc = (const int*)d_in[2];
    float* o = (float*)d_out;
    k_main<<<NBLK, 128>>>(out, gtb, gtc);
    k_finalize<<<1, 32>>>(o);
}